// round 8
// baseline (speedup 1.0000x reference)
#include <cuda_runtime.h>
#include <cuda_bf16.h>
#include <math.h>

#define NB 128
#define NC 32
#define HW 16
#define NE 4096
#define FSZ (NB*NC*HW*HW)   // 1048576
#define PVCAP (256*1024)

typedef unsigned long long u64;

static const int h_PNS[10] = {1,2,3,4,5,6,8,10,13,16};

// ---------------- scratch (device globals; no allocation) ----------------
__device__ float g_cbn[NE*NC];        // normalized codebook
__device__ float g_frest[FSZ];        // residual
__device__ float g_x[FSZ];            // tokens [ntok][32] (pn=4,5,6 only)
__device__ float g_pv[PVCAP];         // partial argmax values
__device__ int   g_pi[PVCAP];         // partial argmax indices
__device__ int   g_hist[NE];          // last-scale histogram
__device__ float g_part[10*NB];       // per (scale, b) sum of squares

__device__ __forceinline__ u64 ffma2(u64 a, u64 b, u64 c) {
    u64 d; asm("fma.rn.f32x2 %0, %1, %2, %3;" : "=l"(d) : "l"(a), "l"(b), "l"(c));
    return d;
}
__device__ __forceinline__ u64 fadd2(u64 a, u64 b) {
    u64 d; asm("add.rn.f32x2 %0, %1, %2;" : "=l"(d) : "l"(a), "l"(b));
    return d;
}
__device__ __forceinline__ u64 pack2(float lo, float hi) {
    u64 d; asm("mov.b64 %0, {%1, %2};" : "=l"(d) : "f"(lo), "f"(hi));
    return d;
}

// ------- init: f_rest <- f_input, zero out/hist, normalize codebook -------
__global__ void k_init(const float* __restrict__ fin, const float* __restrict__ cb,
                       float* __restrict__ out, int out_size) {
    int i = blockIdx.x * 256 + threadIdx.x;
    if (i < FSZ) g_frest[i] = fin[i];
    if (i < out_size) out[i] = 0.0f;
    if (i < NE) {
        g_hist[i] = 0;
        const float* r = cb + (size_t)i * NC;
        float s = 0.f;
#pragma unroll
        for (int c = 0; c < NC; c++) s += r[c] * r[c];
        float inv = 1.0f / fmaxf(sqrtf(s), 1e-12f);
        float* w = g_cbn + (size_t)i * NC;
#pragma unroll
        for (int c = 0; c < NC; c++) w[c] = r[c] * inv;
    }
}

// ---------------- area downsample f_rest -> tokens (pn = 4,5,6 only) -------------
__global__ void k_down(int pn) {
    int t = blockIdx.x * 256 + threadIdx.x;
    int pnpn = pn * pn;
    int ntot = NB * pnpn * NC;
    if (t >= ntot) return;
    int c = t & 31, token = t >> 5;
    int b = token / pnpn, p = token - b * pnpn;
    int py = p / pn, px = p - py * pn;
    int ys = (py * HW) / pn, ye = ((py + 1) * HW + pn - 1) / pn;
    int xs = (px * HW) / pn, xe = ((px + 1) * HW + pn - 1) / pn;
    const float* base = g_frest + ((size_t)(b * NC + c)) * (HW * HW);
    float s = 0.f;
    for (int y = ys; y < ye; y++)
        for (int x = xs; x < xe; x++) s += base[y * HW + x];
    g_x[(size_t)token * NC + c] = s / (float)((ye - ys) * (xe - xs));
}

// ---------------- argmax: smem-tiled, T tokens per thread, f32x2 packed ----------
// grid = (ceil(ntok/(128*T)), CS), block = 128. cpb = 4096/CS (multiple of 128).
// pn >= 8: compute tokens inline from g_frest (windows <= 2x2); else read g_x.
template<int T>
__global__ __launch_bounds__(128) void k_argmax_t(int ntok, int cpb, int pn) {
    __shared__ float s_cb[128 * NC];
    int tid = threadIdx.x;
    int cbase = blockIdx.y * cpb;
    int tokbase = blockIdx.x * (128 * T) + tid;

    u64 tk[T][16];
    float bv[T]; int bi[T]; bool vld[T];
#pragma unroll
    for (int t = 0; t < T; t++) {
        int tok = tokbase + t * 128;
        vld[t] = tok < ntok;
        bv[t] = -3.4e38f; bi[t] = cbase;
#pragma unroll
        for (int i = 0; i < 16; i++) tk[t][i] = 0ULL;
        if (vld[t]) {
            if (pn >= 8) {
                int pnpn = pn * pn;
                int b = tok / pnpn, p = tok - b * pnpn;
                int py = p / pn, px = p - py * pn;
                int ys = (py * HW) / pn, ye = ((py + 1) * HW + pn - 1) / pn;
                int xs = (px * HW) / pn, xe = ((px + 1) * HW + pn - 1) / pn;
                float cnt = (float)((ye - ys) * (xe - xs));
                const float* base = g_frest + (size_t)b * 8192;
                float tkf[32];
#pragma unroll
                for (int c = 0; c < 32; c++) {
                    const float* bc = base + c * 256;
                    float s = 0.f;
                    for (int y = ys; y < ye; y++)
                        for (int x = xs; x < xe; x++) s += bc[y * 16 + x];
                    tkf[c] = s / cnt;
                }
#pragma unroll
                for (int i = 0; i < 16; i++)
                    tk[t][i] = pack2(tkf[2 * i], tkf[2 * i + 1]);
            } else {
                const ulonglong2* p = (const ulonglong2*)(g_x + (size_t)tok * NC);
#pragma unroll
                for (int i = 0; i < 8; i++) {
                    ulonglong2 v = p[i];
                    tk[t][2 * i] = v.x; tk[t][2 * i + 1] = v.y;
                }
            }
        }
    }

    for (int tile = 0; tile < cpb; tile += 128) {
        __syncthreads();
        {
            const float4* src = (const float4*)(g_cbn + (size_t)(cbase + tile) * NC);
            float4* dst = (float4*)s_cb;
#pragma unroll
            for (int i = 0; i < 8; i++) dst[tid + i * 128] = src[tid + i * 128];
        }
        __syncthreads();
        for (int j = 0; j < 128; j++) {
            const ulonglong2* cr = (const ulonglong2*)(s_cb + j * NC);
            u64 c[16];
#pragma unroll
            for (int i = 0; i < 8; i++) {
                ulonglong2 v = cr[i];
                c[2 * i] = v.x; c[2 * i + 1] = v.y;
            }
            int code = cbase + tile + j;
#pragma unroll
            for (int t = 0; t < T; t++) {
                u64 p0 = 0ULL, p1 = 0ULL;
#pragma unroll
                for (int i = 0; i < 8; i++) {
                    p0 = ffma2(c[2 * i],     tk[t][2 * i],     p0);
                    p1 = ffma2(c[2 * i + 1], tk[t][2 * i + 1], p1);
                }
                u64 ps = fadd2(p0, p1);
                float2 pf = *(float2*)&ps;
                float d = pf.x + pf.y;
                if (d > bv[t]) { bv[t] = d; bi[t] = code; }
            }
        }
    }
    int CS = gridDim.y, cs = blockIdx.y;
#pragma unroll
    for (int t = 0; t < T; t++) {
        int tok = tokbase + t * 128;
        if (vld[t]) {
            g_pv[(size_t)tok * CS + cs] = bv[t];
            g_pi[(size_t)tok * CS + cs] = bi[t];
        }
    }
}

// -------- fused: [small: tokens+argmax | combine] -> gather -> up -> conv -> update --
// one block per batch image b; 256 threads.
#define SW_OFF   0
#define SB_OFF   9216
#define HUP_OFF  (9216+32)
#define HS_OFF   (HUP_OFF+10400)
#define WT_OFF   (HS_OFF+8192)
#define JT_OFF   (WT_OFF+64)
#define RED_OFF  (JT_OFF+64)
#define IDX_OFF  (RED_OFF+8)
#define BV_OFF   (IDX_OFF+256)
#define BI_OFF   (BV_OFF+256)
#define SMEM_FLOATS (BI_OFF+256)

__global__ __launch_bounds__(256) void k_fused(
    const float* __restrict__ fin, float* __restrict__ fhat,
    const float* __restrict__ cb, const float* __restrict__ phiw,
    const float* __restrict__ phib, int si, int pn, int k, int last, int CS) {
    extern __shared__ float sm[];
    float* s_w   = sm + SW_OFF;
    float* s_b   = sm + SB_OFF;
    float* s_hup = sm + HUP_OFF;   // [32][325] (18x18 halo, padded stride)
    float* s_hs  = sm + HS_OFF;    // tokens [p][c] then gathered codes [p][c]
    float* s_wt  = sm + WT_OFF;    // bicubic weights [16][4]
    int*   s_jt  = (int*)(sm + JT_OFF);
    float* s_red = sm + RED_OFF;
    int*   s_idx = (int*)(sm + IDX_OFF);
    float* s_bv  = sm + BV_OFF;
    int*   s_bi  = (int*)(sm + BI_OFF);

    int tid = threadIdx.x;
    int b = blockIdx.x;
    int pnpn = pn * pn;
    int small = (pnpn <= 9);

    // ---- phase A: weights/bias, halo zero, bicubic tables; tokens (small) ----
    {
        const float4* wsrc = (const float4*)(phiw + (size_t)k * 9216);
        float4* wdst = (float4*)s_w;
        for (int i = tid; i < 2304; i += 256) wdst[i] = wsrc[i];
        if (tid < 32) s_b[tid] = phib[k * 32 + tid];
    }
    for (int i = tid; i < 10400; i += 256) s_hup[i] = 0.f;

    if (tid < 64) {  // last scale ignores these tables
        int i = tid >> 2, off = (tid & 3) - 1;
        double src = (i + 0.5) * (double)pn / 16.0 - 0.5;
        double i0 = floor(src);
        double f = src - i0;
        double t = fabs(f - (double)off);
        double w;
        if (t <= 1.0)      w = (1.25 * t - 2.25) * t * t + 1.0;
        else if (t < 2.0)  w = (((t - 5.0) * t + 8.0) * t - 4.0) * (-0.75);
        else               w = 0.0;
        int j = (int)i0 + off;
        j = min(max(j, 0), pn - 1);
        s_wt[tid] = (float)w;
        s_jt[tid] = j;
    }

    if (small) {
        // area-downsample this image's tokens into s_hs[p][c]
        const float* base = g_frest + (size_t)b * 8192;
        for (int t = tid; t < pnpn * 32; t += 256) {
            int c = t & 31, p = t >> 5;
            int py = p / pn, px = p - py * pn;
            int ys = (py * HW) / pn, ye = ((py + 1) * HW + pn - 1) / pn;
            int xs = (px * HW) / pn, xe = ((px + 1) * HW + pn - 1) / pn;
            const float* bc = base + c * 256;
            float s = 0.f;
            for (int y = ys; y < ye; y++)
                for (int x = xs; x < xe; x++) s += bc[y * 16 + x];
            s_hs[p * 32 + c] = s / (float)((ye - ys) * (xe - xs));
        }
        __syncthreads();
        // argmax: thread = (token, code-slice); all 256 threads active
        int tok = tid % pnpn, kk = tid / pnpn;
        int nk = (255 - tok) / pnpn + 1;
        u64 tk[16];
        const ulonglong2* tp = (const ulonglong2*)(s_hs + tok * 32);
#pragma unroll
        for (int i = 0; i < 8; i++) {
            ulonglong2 v = tp[i];
            tk[2 * i] = v.x; tk[2 * i + 1] = v.y;
        }
        int c0 = (kk * NE) / nk, c1 = ((kk + 1) * NE) / nk;
        float bvv = -3.4e38f; int bii = c0;
        for (int c = c0; c < c1; c++) {
            const ulonglong2* cr = (const ulonglong2*)(g_cbn + (size_t)c * NC);
            u64 p0 = 0ULL, p1 = 0ULL;
#pragma unroll
            for (int i = 0; i < 8; i++) {
                ulonglong2 v = cr[i];
                p0 = ffma2(v.x, tk[2 * i], p0);
                p1 = ffma2(v.y, tk[2 * i + 1], p1);
            }
            u64 ps = fadd2(p0, p1);
            float2 pf = *(float2*)&ps;
            float d = pf.x + pf.y;
            if (d > bvv) { bvv = d; bii = c; }
        }
        s_bv[tid] = bvv; s_bi[tid] = bii;
        __syncthreads();
        if (tid < pnpn) {
            float v0 = s_bv[tid]; int i0 = s_bi[tid];
            for (int q = tid + pnpn; q < 256; q += pnpn) {
                float v = s_bv[q]; int i2 = s_bi[q];
                if (v > v0 || (v == v0 && i2 < i0)) { v0 = v; i0 = i2; }
            }
            s_idx[tid] = i0;
        }
    } else {
        // combine code-split argmax partials (+ histogram on last scale)
        for (int p = tid; p < pnpn; p += 256) {
            size_t tb = (size_t)(b * pnpn + p) * CS;
            float bvv = g_pv[tb]; int bii = g_pi[tb];
            for (int cs = 1; cs < CS; cs++) {
                float v = g_pv[tb + cs]; int i2 = g_pi[tb + cs];
                if (v > bvv || (v == bvv && i2 < bii)) { bvv = v; bii = i2; }
            }
            s_idx[p] = bii;
            if (last) atomicAdd(&g_hist[bii], 1);
        }
    }
    __syncthreads();

    if (!last) {
        for (int t = tid; t < pnpn * 32; t += 256) {
            int p = t >> 5, c = t & 31;
            s_hs[t] = cb[(size_t)s_idx[p] * NC + c];
        }
        __syncthreads();
    }

    // build h_up (interior of halo'd image)
    if (last) {
        for (int o = tid; o < 8192; o += 256) {
            int c = o & 31, pix = o >> 5;
            int y = pix >> 4, x = pix & 15;
            s_hup[c * 325 + (y + 1) * 18 + (x + 1)] =
                cb[(size_t)s_idx[pix] * NC + c];
        }
    } else {
        for (int o = tid; o < 8192; o += 256) {
            int c = o & 31, pix = o >> 5;
            int y = pix >> 4, x = pix & 15;
            float acc = 0.f;
#pragma unroll
            for (int ty = 0; ty < 4; ty++) {
                float wy = s_wt[y * 4 + ty];
                int jy = s_jt[y * 4 + ty];
                const float* row = s_hs + (jy * pn) * 32 + c;
                float rs = 0.f;
#pragma unroll
                for (int tx = 0; tx < 4; tx++)
                    rs = fmaf(s_wt[x * 4 + tx], row[s_jt[x * 4 + tx] * 32], rs);
                acc = fmaf(wy, rs, acc);
            }
            s_hup[c * 325 + (y + 1) * 18 + (x + 1)] = acc;
        }
    }
    __syncthreads();

    // 3x3 conv: warp wi owns co in [4wi, 4wi+4); lane -> (y = lane>>1, xs = (lane&1)*8)
    int wi = tid >> 5, lane = tid & 31;
    int y = lane >> 1, xs = (lane & 1) * 8;
    float acc[4][8];
#pragma unroll
    for (int a = 0; a < 4; a++)
#pragma unroll
        for (int o = 0; o < 8; o++) acc[a][o] = 0.f;

    for (int ci = 0; ci < 32; ci++) {
        float tp[3][10];
        const float* hp = s_hup + ci * 325 + y * 18 + xs;
#pragma unroll
        for (int r = 0; r < 3; r++)
#pragma unroll
            for (int cc = 0; cc < 10; cc++) tp[r][cc] = hp[r * 18 + cc];
#pragma unroll
        for (int co4 = 0; co4 < 4; co4++) {
            const float* wp = s_w + ((size_t)(wi * 4 + co4) * 32 + ci) * 9;
            float w0 = wp[0], w1 = wp[1], w2 = wp[2];
            float w3 = wp[3], w4 = wp[4], w5 = wp[5];
            float w6 = wp[6], w7 = wp[7], w8 = wp[8];
#pragma unroll
            for (int xo = 0; xo < 8; xo++) {
                float s = acc[co4][xo];
                s = fmaf(w0, tp[0][xo],     s);
                s = fmaf(w1, tp[0][xo + 1], s);
                s = fmaf(w2, tp[0][xo + 2], s);
                s = fmaf(w3, tp[1][xo],     s);
                s = fmaf(w4, tp[1][xo + 1], s);
                s = fmaf(w5, tp[1][xo + 2], s);
                s = fmaf(w6, tp[2][xo],     s);
                s = fmaf(w7, tp[2][xo + 1], s);
                s = fmaf(w8, tp[2][xo + 2], s);
                acc[co4][xo] = s;
            }
        }
    }

    // h = 0.5*h_up + 0.5*(conv + bias); update f_hat, f_rest; accumulate MSE
    float sq = 0.f;
    const float* finb = fin + (size_t)b * 8192;
    float* fhb = fhat + (size_t)b * 8192;
    float* frb = g_frest + (size_t)b * 8192;
#pragma unroll
    for (int co4 = 0; co4 < 4; co4++) {
        int co = wi * 4 + co4;
        float bias = s_b[co];
#pragma unroll
        for (int xo = 0; xo < 8; xo++) {
            int x = xs + xo;
            float conv = acc[co4][xo] + bias;
            float hu = s_hup[co * 325 + (y + 1) * 18 + (x + 1)];
            float h = 0.5f * hu + 0.5f * conv;
            int g = co * 256 + y * 16 + x;
            float fh = fhb[g] + h;
            fhb[g] = fh;
            frb[g] = frb[g] - h;
            float d = fh - finb[g];
            sq = fmaf(d, d, sq);
        }
    }
#pragma unroll
    for (int o = 16; o; o >>= 1) sq += __shfl_down_sync(0xffffffffu, sq, o);
    if (lane == 0) s_red[wi] = sq;
    __syncthreads();
    if (tid == 0) {
        float s = 0.f;
        for (int i = 0; i < 8; i++) s += s_red[i];
        g_part[si * NB + b] = s;
    }
}

// ---------------- finalize: loss + perplexity ----------------
__global__ void k_final(float* __restrict__ out, int out_size) {
    __shared__ float sr[256];
    int tid = threadIdx.x;
    float s = 0.f;
    for (int i = tid; i < 10 * NB; i += 256) s += g_part[i];
    sr[tid] = s;
    __syncthreads();
    for (int o = 128; o; o >>= 1) {
        if (tid < o) sr[tid] += sr[tid + o];
        __syncthreads();
    }
    float lossv = 0.f;
    if (tid == 0) lossv = sr[0] * (1.25f / (10.0f * (float)FSZ));
    __syncthreads();

    float e = 0.f;
    for (int i = tid; i < NE; i += 256) {
        float p = (float)g_hist[i] * (1.0f / 32768.0f);
        e += p * logf(p + 1e-10f);
    }
    sr[tid] = e;
    __syncthreads();
    for (int o = 128; o; o >>= 1) {
        if (tid < o) sr[tid] += sr[tid + o];
        __syncthreads();
    }
    if (tid == 0) {
        out[out_size - 2] = lossv;
        out[out_size - 1] = expf(-sr[0]);
    }
}

// ---------------- launcher ----------------
extern "C" void kernel_launch(void* const* d_in, const int* in_sizes, int n_in,
                              void* d_out, int out_size) {
    // Identify inputs BY SIZE (robust to metadata ordering):
    //   f_input 1048576, codebook 131072, phi_w 36864, phi_b 128
    const float* fin  = nullptr;
    const float* cb   = nullptr;
    const float* phiw = nullptr;
    const float* phib = nullptr;
    for (int i = 0; i < n_in; i++) {
        int sz = in_sizes[i];
        if      (sz == FSZ)        fin  = (const float*)d_in[i];
        else if (sz == NE * NC)    cb   = (const float*)d_in[i];
        else if (sz == 4*NC*NC*9)  phiw = (const float*)d_in[i];
        else if (sz == 4*NC)       phib = (const float*)d_in[i];
    }
    float* out = (float*)d_out;

    // PhiPartiallyShared tick schedule, replicating numpy float64 exactly.
    int phik[10];
    {
        double start = 1.0 / 12.0;
        double stop  = 1.0 - 1.0 / 12.0;
        double step  = (stop - start) / 3.0;
        double ticks[4];
        ticks[0] = start;
        ticks[1] = 1.0 * step + start;
        ticks[2] = 2.0 * step + start;
        ticks[3] = stop;
        for (int si = 0; si < 10; si++) {
            double v = (double)si / 9.0;
            int best = 0;
            double bd = fabs(ticks[0] - v);
            for (int kk = 1; kk < 4; kk++) {
                double d = fabs(ticks[kk] - v);
                if (d < bd) { bd = d; best = kk; }
            }
            phik[si] = best;
        }
    }

    cudaFuncSetAttribute(k_fused, cudaFuncAttributeMaxDynamicSharedMemorySize,
                         SMEM_FLOATS * 4);

    int initN = (FSZ > out_size ? FSZ : out_size);
    k_init<<<(initN + 255) / 256, 256>>>(fin, cb, out, out_size);

    for (int si = 0; si < 10; si++) {
        int pn = h_PNS[si];
        int ntok = NB * pn * pn;
        int last = (si == 9);
        int CS = 1;

        if (pn >= 4 && pn <= 6) k_down<<<(ntok * NC + 255) / 256, 256>>>(pn);

        if (ntok >= 4608) {
            // T = 4 tokens/thread: 512 tokens per block (pn >= 6)
            int tb = (ntok + 511) / 512;
            CS = 1;
            while (tb * CS < 296 && CS < 32) CS <<= 1;
            dim3 g(tb, CS);
            k_argmax_t<4><<<g, 128>>>(ntok, NE / CS, pn);
        } else if (pn >= 4) {
            // T = 1 token/thread: 128 tokens per block (pn = 4,5)
            int tb = ntok / 128;
            CS = 1;
            while (tb * CS < 296 && CS < 32) CS <<= 1;
            dim3 g(tb, CS);
            k_argmax_t<1><<<g, 128>>>(ntok, NE / CS, 0);
        }
        // pn <= 3: argmax happens inside k_fused

        k_fused<<<NB, 256, SMEM_FLOATS * 4>>>(fin, out, cb, phiw, phib,
                                              si, pn, phik[si], last, CS);
    }
    k_final<<<1, 256>>>(out, out_size);
}

// round 9
// speedup vs baseline: 1.4241x; 1.4241x over previous
#include <cuda_runtime.h>
#include <cuda_bf16.h>
#include <math.h>

#define NB 128
#define NC 32
#define HW 16
#define NE 4096
#define FSZ (NB*NC*HW*HW)   // 1048576
#define PVCAP (256*1024)

typedef unsigned long long u64;

static const int h_PNS[10] = {1,2,3,4,5,6,8,10,13,16};

// ---------------- scratch (device globals; no allocation) ----------------
__device__ float g_cbn[NE*NC];        // normalized codebook
__device__ float g_frest[FSZ];        // residual
__device__ float g_x[FSZ];            // tokens [ntok][32]
__device__ float g_pv[PVCAP];         // partial argmax values
__device__ int   g_pi[PVCAP];         // partial argmax indices
__device__ int   g_hist[NE];          // last-scale histogram
__device__ float g_part[10*NB];       // per (scale, b) sum of squares

__device__ __forceinline__ u64 ffma2(u64 a, u64 b, u64 c) {
    u64 d; asm("fma.rn.f32x2 %0, %1, %2, %3;" : "=l"(d) : "l"(a), "l"(b), "l"(c));
    return d;
}
__device__ __forceinline__ u64 fadd2(u64 a, u64 b) {
    u64 d; asm("add.rn.f32x2 %0, %1, %2;" : "=l"(d) : "l"(a), "l"(b));
    return d;
}

// ------- init: f_rest <- f_input, zero out/hist, normalize codebook -------
__global__ void k_init(const float* __restrict__ fin, const float* __restrict__ cb,
                       float* __restrict__ out, int out_size) {
    int i = blockIdx.x * 256 + threadIdx.x;
    if (i < FSZ) g_frest[i] = fin[i];
    if (i < out_size) out[i] = 0.0f;
    if (i < NE) {
        g_hist[i] = 0;
        const float* r = cb + (size_t)i * NC;
        float s = 0.f;
#pragma unroll
        for (int c = 0; c < NC; c++) s += r[c] * r[c];
        float inv = 1.0f / fmaxf(sqrtf(s), 1e-12f);
        float* w = g_cbn + (size_t)i * NC;
#pragma unroll
        for (int c = 0; c < NC; c++) w[c] = r[c] * inv;
    }
}

// ---------------- area downsample f_rest -> tokens [ntok][C] ----------------
__global__ void k_down(int pn) {
    int t = blockIdx.x * 256 + threadIdx.x;
    int pnpn = pn * pn;
    int ntot = NB * pnpn * NC;
    if (t >= ntot) return;
    int c = t & 31, token = t >> 5;
    int b = token / pnpn, p = token - b * pnpn;
    int py = p / pn, px = p - py * pn;
    int ys = (py * HW) / pn, ye = ((py + 1) * HW + pn - 1) / pn;
    int xs = (px * HW) / pn, xe = ((px + 1) * HW + pn - 1) / pn;
    const float* base = g_frest + ((size_t)(b * NC + c)) * (HW * HW);
    float s = 0.f;
    for (int y = ys; y < ye; y++)
        for (int x = xs; x < xe; x++) s += base[y * HW + x];
    g_x[(size_t)token * NC + c] = s / (float)((ye - ys) * (xe - xs));
}

// ---------------- argmax: smem-tiled, T tokens per thread, f32x2 packed ----------
// grid = (ceil(ntok/(128*T)), CS), block = 128. cpb = 4096/CS (multiple of 128).
// pn16 != 0: read tokens transposed from g_frest (last scale, no k_down needed).
template<int T>
__global__ __launch_bounds__(128) void k_argmax_t(int ntok, int cpb, int pn16) {
    __shared__ float s_cb[128 * NC];
    int tid = threadIdx.x;
    int cbase = blockIdx.y * cpb;
    int tokbase = blockIdx.x * (128 * T) + tid;

    u64 tk[T][16];
    float bv[T]; int bi[T]; bool vld[T];
#pragma unroll
    for (int t = 0; t < T; t++) {
        int tok = tokbase + t * 128;
        vld[t] = tok < ntok;
        bv[t] = -3.4e38f; bi[t] = cbase;
#pragma unroll
        for (int i = 0; i < 16; i++) tk[t][i] = 0ULL;
        if (vld[t]) {
            if (pn16) {
                int b = tok >> 8, pix = tok & 255;
                const float* fr = g_frest + (size_t)b * 8192 + pix;
#pragma unroll
                for (int i = 0; i < 16; i++) {
                    float2 v;
                    v.x = fr[(2 * i) * 256];
                    v.y = fr[(2 * i + 1) * 256];
                    tk[t][i] = *(u64*)&v;
                }
            } else {
                const ulonglong2* p = (const ulonglong2*)(g_x + (size_t)tok * NC);
#pragma unroll
                for (int i = 0; i < 8; i++) {
                    ulonglong2 v = p[i];
                    tk[t][2 * i] = v.x; tk[t][2 * i + 1] = v.y;
                }
            }
        }
    }

    for (int tile = 0; tile < cpb; tile += 128) {
        __syncthreads();
        {
            const float4* src = (const float4*)(g_cbn + (size_t)(cbase + tile) * NC);
            float4* dst = (float4*)s_cb;
#pragma unroll
            for (int i = 0; i < 8; i++) dst[tid + i * 128] = src[tid + i * 128];
        }
        __syncthreads();
        for (int j = 0; j < 128; j++) {
            const ulonglong2* cr = (const ulonglong2*)(s_cb + j * NC);
            u64 c[16];
#pragma unroll
            for (int i = 0; i < 8; i++) {
                ulonglong2 v = cr[i];
                c[2 * i] = v.x; c[2 * i + 1] = v.y;
            }
            int code = cbase + tile + j;
#pragma unroll
            for (int t = 0; t < T; t++) {
                u64 p0 = 0ULL, p1 = 0ULL;
#pragma unroll
                for (int i = 0; i < 8; i++) {
                    p0 = ffma2(c[2 * i],     tk[t][2 * i],     p0);
                    p1 = ffma2(c[2 * i + 1], tk[t][2 * i + 1], p1);
                }
                u64 ps = fadd2(p0, p1);
                float2 pf = *(float2*)&ps;
                float d = pf.x + pf.y;
                if (d > bv[t]) { bv[t] = d; bi[t] = code; }
            }
        }
    }
    int CS = gridDim.y, cs = blockIdx.y;
#pragma unroll
    for (int t = 0; t < T; t++) {
        int tok = tokbase + t * 128;
        if (vld[t]) {
            g_pv[(size_t)tok * CS + cs] = bv[t];
            g_pi[(size_t)tok * CS + cs] = bi[t];
        }
    }
}

// -------- fused: combine partials -> gather codes -> bicubic up -> 3x3 conv -> update --
// one block per batch image b; 512 threads (16 warps, 2 output channels per warp).
#define SW_OFF   0
#define SB_OFF   9216
#define HUP_OFF  (9216+32)
#define HS_OFF   (HUP_OFF+10400)
#define WT_OFF   (HS_OFF+8192)
#define JT_OFF   (WT_OFF+64)
#define RED_OFF  (JT_OFF+64)
#define IDX_OFF  (RED_OFF+16)
#define SMEM_FLOATS (IDX_OFF+256)

__global__ __launch_bounds__(512) void k_fused(
    const float* __restrict__ fin, float* __restrict__ fhat,
    const float* __restrict__ cb, const float* __restrict__ phiw,
    const float* __restrict__ phib, int si, int pn, int k, int last, int CS) {
    extern __shared__ float sm[];
    float* s_w   = sm + SW_OFF;
    float* s_b   = sm + SB_OFF;
    float* s_hup = sm + HUP_OFF;   // [32][325] (18x18 halo, padded stride)
    float* s_hs  = sm + HS_OFF;    // gathered codes [p][c]
    float* s_wt  = sm + WT_OFF;    // bicubic weights [16][4]
    int*   s_jt  = (int*)(sm + JT_OFF);
    float* s_red = sm + RED_OFF;
    int*   s_idx = (int*)(sm + IDX_OFF);

    int tid = threadIdx.x;
    int b = blockIdx.x;
    int pnpn = pn * pn;

    // combine code-split argmax partials for this image's tokens (+ histogram)
    for (int p = tid; p < pnpn; p += 512) {
        size_t tb = (size_t)(b * pnpn + p) * CS;
        float bvv = g_pv[tb]; int bii = g_pi[tb];
        for (int cs = 1; cs < CS; cs++) {
            float v = g_pv[tb + cs]; int i2 = g_pi[tb + cs];
            if (v > bvv || (v == bvv && i2 < bii)) { bvv = v; bii = i2; }
        }
        s_idx[p] = bii;
        if (last) atomicAdd(&g_hist[bii], 1);
    }

    // load Phi weights/bias
    {
        const float4* wsrc = (const float4*)(phiw + (size_t)k * 9216);
        float4* wdst = (float4*)s_w;
        for (int i = tid; i < 2304; i += 512) wdst[i] = wsrc[i];
        if (tid < 32) s_b[tid] = phib[k * 32 + tid];
    }
    // zero halo image
    for (int i = tid; i < 10400; i += 512) s_hup[i] = 0.f;

    if (!last && tid < 64) {
        int i = tid >> 2, off = (tid & 3) - 1;
        double src = (i + 0.5) * (double)pn / 16.0 - 0.5;
        double i0 = floor(src);
        double f = src - i0;
        double t = fabs(f - (double)off);
        double w;
        if (t <= 1.0)      w = (1.25 * t - 2.25) * t * t + 1.0;
        else if (t < 2.0)  w = (((t - 5.0) * t + 8.0) * t - 4.0) * (-0.75);
        else               w = 0.0;
        int j = (int)i0 + off;
        j = min(max(j, 0), pn - 1);
        s_wt[tid] = (float)w;
        s_jt[tid] = j;
    }
    __syncthreads();

    if (!last) {
        for (int t = tid; t < pnpn * 32; t += 512) {
            int p = t >> 5, c = t & 31;
            s_hs[t] = cb[(size_t)s_idx[p] * NC + c];
        }
        __syncthreads();
    }

    // build h_up (interior of halo'd image)
    if (last) {
        for (int o = tid; o < 8192; o += 512) {
            int c = o & 31, pix = o >> 5;
            int y = pix >> 4, x = pix & 15;
            s_hup[c * 325 + (y + 1) * 18 + (x + 1)] =
                cb[(size_t)s_idx[pix] * NC + c];
        }
    } else {
        for (int o = tid; o < 8192; o += 512) {
            int c = o & 31, pix = o >> 5;
            int y = pix >> 4, x = pix & 15;
            float acc = 0.f;
#pragma unroll
            for (int ty = 0; ty < 4; ty++) {
                float wy = s_wt[y * 4 + ty];
                int jy = s_jt[y * 4 + ty];
                const float* row = s_hs + (jy * pn) * 32 + c;
                float rs = 0.f;
#pragma unroll
                for (int tx = 0; tx < 4; tx++)
                    rs = fmaf(s_wt[x * 4 + tx], row[s_jt[x * 4 + tx] * 32], rs);
                acc = fmaf(wy, rs, acc);
            }
            s_hup[c * 325 + (y + 1) * 18 + (x + 1)] = acc;
        }
    }
    __syncthreads();

    // 3x3 conv: warp wi (0..15) owns co in [2wi, 2wi+2);
    // lane -> (y = lane>>1, xs = (lane&1)*8)
    int wi = tid >> 5, lane = tid & 31;
    int y = lane >> 1, xs = (lane & 1) * 8;
    float acc[2][8];
#pragma unroll
    for (int a = 0; a < 2; a++)
#pragma unroll
        for (int o = 0; o < 8; o++) acc[a][o] = 0.f;

    for (int ci = 0; ci < 32; ci++) {
        float tp[3][10];
        const float* hp = s_hup + ci * 325 + y * 18 + xs;
#pragma unroll
        for (int r = 0; r < 3; r++)
#pragma unroll
            for (int cc = 0; cc < 10; cc++) tp[r][cc] = hp[r * 18 + cc];
#pragma unroll
        for (int co2 = 0; co2 < 2; co2++) {
            const float* wp = s_w + ((size_t)(wi * 2 + co2) * 32 + ci) * 9;
            float w0 = wp[0], w1 = wp[1], w2 = wp[2];
            float w3 = wp[3], w4 = wp[4], w5 = wp[5];
            float w6 = wp[6], w7 = wp[7], w8 = wp[8];
#pragma unroll
            for (int xo = 0; xo < 8; xo++) {
                float s = acc[co2][xo];
                s = fmaf(w0, tp[0][xo],     s);
                s = fmaf(w1, tp[0][xo + 1], s);
                s = fmaf(w2, tp[0][xo + 2], s);
                s = fmaf(w3, tp[1][xo],     s);
                s = fmaf(w4, tp[1][xo + 1], s);
                s = fmaf(w5, tp[1][xo + 2], s);
                s = fmaf(w6, tp[2][xo],     s);
                s = fmaf(w7, tp[2][xo + 1], s);
                s = fmaf(w8, tp[2][xo + 2], s);
                acc[co2][xo] = s;
            }
        }
    }

    // h = 0.5*h_up + 0.5*(conv + bias); update f_hat, f_rest; accumulate MSE
    float sq = 0.f;
    const float* finb = fin + (size_t)b * 8192;
    float* fhb = fhat + (size_t)b * 8192;
    float* frb = g_frest + (size_t)b * 8192;
#pragma unroll
    for (int co2 = 0; co2 < 2; co2++) {
        int co = wi * 2 + co2;
        float bias = s_b[co];
#pragma unroll
        for (int xo = 0; xo < 8; xo++) {
            int x = xs + xo;
            float conv = acc[co2][xo] + bias;
            float hu = s_hup[co * 325 + (y + 1) * 18 + (x + 1)];
            float h = 0.5f * hu + 0.5f * conv;
            int g = co * 256 + y * 16 + x;
            float fh = fhb[g] + h;
            fhb[g] = fh;
            frb[g] = frb[g] - h;
            float d = fh - finb[g];
            sq = fmaf(d, d, sq);
        }
    }
#pragma unroll
    for (int o = 16; o; o >>= 1) sq += __shfl_down_sync(0xffffffffu, sq, o);
    if (lane == 0) s_red[wi] = sq;
    __syncthreads();
    if (tid == 0) {
        float s = 0.f;
        for (int i = 0; i < 16; i++) s += s_red[i];
        g_part[si * NB + b] = s;
    }
}

// ---------------- finalize: loss + perplexity ----------------
__global__ void k_final(float* __restrict__ out, int out_size) {
    __shared__ float sr[256];
    int tid = threadIdx.x;
    float s = 0.f;
    for (int i = tid; i < 10 * NB; i += 256) s += g_part[i];
    sr[tid] = s;
    __syncthreads();
    for (int o = 128; o; o >>= 1) {
        if (tid < o) sr[tid] += sr[tid + o];
        __syncthreads();
    }
    float lossv = 0.f;
    if (tid == 0) lossv = sr[0] * (1.25f / (10.0f * (float)FSZ));
    __syncthreads();

    float e = 0.f;
    for (int i = tid; i < NE; i += 256) {
        float p = (float)g_hist[i] * (1.0f / 32768.0f);
        e += p * logf(p + 1e-10f);
    }
    sr[tid] = e;
    __syncthreads();
    for (int o = 128; o; o >>= 1) {
        if (tid < o) sr[tid] += sr[tid + o];
        __syncthreads();
    }
    if (tid == 0) {
        out[out_size - 2] = lossv;
        out[out_size - 1] = expf(-sr[0]);
    }
}

// ---------------- launcher ----------------
extern "C" void kernel_launch(void* const* d_in, const int* in_sizes, int n_in,
                              void* d_out, int out_size) {
    // Identify inputs BY SIZE (robust to metadata ordering):
    //   f_input 1048576, codebook 131072, phi_w 36864, phi_b 128
    const float* fin  = nullptr;
    const float* cb   = nullptr;
    const float* phiw = nullptr;
    const float* phib = nullptr;
    for (int i = 0; i < n_in; i++) {
        int sz = in_sizes[i];
        if      (sz == FSZ)        fin  = (const float*)d_in[i];
        else if (sz == NE * NC)    cb   = (const float*)d_in[i];
        else if (sz == 4*NC*NC*9)  phiw = (const float*)d_in[i];
        else if (sz == 4*NC)       phib = (const float*)d_in[i];
    }
    float* out = (float*)d_out;

    // PhiPartiallyShared tick schedule, replicating numpy float64 exactly.
    int phik[10];
    {
        double start = 1.0 / 12.0;
        double stop  = 1.0 - 1.0 / 12.0;
        double step  = (stop - start) / 3.0;
        double ticks[4];
        ticks[0] = start;
        ticks[1] = 1.0 * step + start;
        ticks[2] = 2.0 * step + start;
        ticks[3] = stop;
        for (int si = 0; si < 10; si++) {
            double v = (double)si / 9.0;
            int best = 0;
            double bd = fabs(ticks[0] - v);
            for (int kk = 1; kk < 4; kk++) {
                double d = fabs(ticks[kk] - v);
                if (d < bd) { bd = d; best = kk; }
            }
            phik[si] = best;
        }
    }

    cudaFuncSetAttribute(k_fused, cudaFuncAttributeMaxDynamicSharedMemorySize,
                         SMEM_FLOATS * 4);

    int initN = (FSZ > out_size ? FSZ : out_size);
    k_init<<<(initN + 255) / 256, 256>>>(fin, cb, out, out_size);

    for (int si = 0; si < 10; si++) {
        int pn = h_PNS[si];
        int ntok = NB * pn * pn;
        int last = (si == 9);

        if (!last) k_down<<<(ntok * NC + 255) / 256, 256>>>(pn);

        int CS;
        if (ntok >= 4608) {
            // T = 4 tokens/thread: 512 tokens per block
            int tb = (ntok + 511) / 512;
            CS = 1;
            while (tb * CS < 296 && CS < 32) CS <<= 1;
            dim3 g(tb, CS);
            k_argmax_t<4><<<g, 128>>>(ntok, NE / CS, last ? 1 : 0);
        } else {
            // T = 1 token/thread: 128 tokens per block
            int tb = ntok / 128;
            CS = 1;
            while (tb * CS < 296 && CS < 32) CS <<= 1;
            dim3 g(tb, CS);
            k_argmax_t<1><<<g, 128>>>(ntok, NE / CS, 0);
        }

        k_fused<<<NB, 512, SMEM_FLOATS * 4>>>(fin, out, cb, phiw, phib,
                                              si, pn, phik[si], last, CS);
    }
    k_final<<<1, 256>>>(out, out_size);
}

// round 10
// speedup vs baseline: 1.4563x; 1.0226x over previous
#include <cuda_runtime.h>
#include <cuda_bf16.h>
#include <math.h>

#define NB 128
#define NC 32
#define HW 16
#define NE 4096
#define FSZ (NB*NC*HW*HW)   // 1048576
#define PVCAP (256*1024)

typedef unsigned long long u64;

static const int h_PNS[10] = {1,2,3,4,5,6,8,10,13,16};

// ---------------- scratch (device globals; no allocation) ----------------
__device__ float g_cbn[NE*NC];        // normalized codebook
__device__ float g_frest[FSZ];        // residual
__device__ float g_x[FSZ];            // tokens [ntok][32]
__device__ float g_pv[PVCAP];         // partial argmax values
__device__ int   g_pi[PVCAP];         // partial argmax indices
__device__ int   g_hist[NE];          // last-scale histogram
__device__ float g_part[10*2*NB];     // per (scale, block) sum of squares

__device__ __forceinline__ u64 ffma2(u64 a, u64 b, u64 c) {
    u64 d; asm("fma.rn.f32x2 %0, %1, %2, %3;" : "=l"(d) : "l"(a), "l"(b), "l"(c));
    return d;
}
__device__ __forceinline__ u64 fadd2(u64 a, u64 b) {
    u64 d; asm("add.rn.f32x2 %0, %1, %2;" : "=l"(d) : "l"(a), "l"(b));
    return d;
}

// --- init: f_rest <- f_input, zero out/hist, normalize codebook, pn=1 tokens ---
__global__ void k_init(const float* __restrict__ fin, const float* __restrict__ cb,
                       float* __restrict__ out, int out_size) {
    int i = blockIdx.x * 256 + threadIdx.x;
    if (i < FSZ) g_frest[i] = fin[i];
    if (i < out_size) out[i] = 0.0f;
    if (i < NE) {
        g_hist[i] = 0;
        const float* r = cb + (size_t)i * NC;
        float s = 0.f;
#pragma unroll
        for (int c = 0; c < NC; c++) s += r[c] * r[c];
        float inv = 1.0f / fmaxf(sqrtf(s), 1e-12f);
        float* w = g_cbn + (size_t)i * NC;
#pragma unroll
        for (int c = 0; c < NC; c++) w[c] = r[c] * inv;
    }
    // pn=1 tokens: g_x[b*32+c] = mean over 256 pixels of fin[b][c]
    if (i < NB * NC) {
        const float* base = fin + (size_t)i * 256;
        float s = 0.f;
        for (int p = 0; p < 256; p++) s += base[p];
        g_x[i] = s * (1.0f / 256.0f);
    }
}

// ---------------- argmax: smem-tiled, T tokens per thread, f32x2 packed ----------
// grid = (ceil(ntok/(128*T)), CS), block = 128. cpb = 4096/CS (multiple of 128).
// pn16 != 0: read tokens transposed from g_frest (last scale).
template<int T>
__global__ __launch_bounds__(128) void k_argmax_t(int ntok, int cpb, int pn16) {
    __shared__ float s_cb[128 * NC];
    int tid = threadIdx.x;
    int cbase = blockIdx.y * cpb;
    int tokbase = blockIdx.x * (128 * T) + tid;

    u64 tk[T][16];
    float bv[T]; int bi[T]; bool vld[T];
#pragma unroll
    for (int t = 0; t < T; t++) {
        int tok = tokbase + t * 128;
        vld[t] = tok < ntok;
        bv[t] = -3.4e38f; bi[t] = cbase;
#pragma unroll
        for (int i = 0; i < 16; i++) tk[t][i] = 0ULL;
        if (vld[t]) {
            if (pn16) {
                int b = tok >> 8, pix = tok & 255;
                const float* fr = g_frest + (size_t)b * 8192 + pix;
#pragma unroll
                for (int i = 0; i < 16; i++) {
                    float2 v;
                    v.x = fr[(2 * i) * 256];
                    v.y = fr[(2 * i + 1) * 256];
                    tk[t][i] = *(u64*)&v;
                }
            } else {
                const ulonglong2* p = (const ulonglong2*)(g_x + (size_t)tok * NC);
#pragma unroll
                for (int i = 0; i < 8; i++) {
                    ulonglong2 v = p[i];
                    tk[t][2 * i] = v.x; tk[t][2 * i + 1] = v.y;
                }
            }
        }
    }

    for (int tile = 0; tile < cpb; tile += 128) {
        __syncthreads();
        {
            const float4* src = (const float4*)(g_cbn + (size_t)(cbase + tile) * NC);
            float4* dst = (float4*)s_cb;
#pragma unroll
            for (int i = 0; i < 8; i++) dst[tid + i * 128] = src[tid + i * 128];
        }
        __syncthreads();
        for (int j = 0; j < 128; j++) {
            const ulonglong2* cr = (const ulonglong2*)(s_cb + j * NC);
            u64 c[16];
#pragma unroll
            for (int i = 0; i < 8; i++) {
                ulonglong2 v = cr[i];
                c[2 * i] = v.x; c[2 * i + 1] = v.y;
            }
            int code = cbase + tile + j;
#pragma unroll
            for (int t = 0; t < T; t++) {
                u64 p0 = 0ULL, p1 = 0ULL;
#pragma unroll
                for (int i = 0; i < 8; i++) {
                    p0 = ffma2(c[2 * i],     tk[t][2 * i],     p0);
                    p1 = ffma2(c[2 * i + 1], tk[t][2 * i + 1], p1);
                }
                u64 ps = fadd2(p0, p1);
                float2 pf = *(float2*)&ps;
                float d = pf.x + pf.y;
                if (d > bv[t]) { bv[t] = d; bi[t] = code; }
            }
        }
    }
    int CS = gridDim.y, cs = blockIdx.y;
#pragma unroll
    for (int t = 0; t < T; t++) {
        int tok = tokbase + t * 128;
        if (vld[t]) {
            g_pv[(size_t)tok * CS + cs] = bv[t];
            g_pi[(size_t)tok * CS + cs] = bi[t];
        }
    }
}

// -------- fused: combine -> gather -> bicubic up -> 3x3 conv (16 co) -> update
//          -> next-scale tokens.  grid = 2*NB (2 blocks per image), 256 threads.
#define SW_OFF   0                    // 4608 : this block's 16 co of phi weights
#define SB_OFF   4608                 // 32
#define HUP_OFF  4640                 // 10400 : halo'd h_up [32][325]
#define HS_OFF   15040                // 8192  : gathered codes [p][c]
#define WT_OFF   23232                // 64
#define JT_OFF   23296                // 64
#define RED_OFF  23360                // 16
#define IDX_OFF  23376                // 256
#define SMEM_FLOATS 23632             // 94528 bytes -> 2 blocks/SM

__global__ __launch_bounds__(256) void k_fused(
    const float* __restrict__ fin, float* __restrict__ fhat,
    const float* __restrict__ cb, const float* __restrict__ phiw,
    const float* __restrict__ phib, int si, int pn, int k, int last, int CS,
    int next_pn) {
    extern __shared__ float sm[];
    float* s_w   = sm + SW_OFF;
    float* s_b   = sm + SB_OFF;
    float* s_hup = sm + HUP_OFF;
    float* s_hs  = sm + HS_OFF;
    float* s_wt  = sm + WT_OFF;
    int*   s_jt  = (int*)(sm + JT_OFF);
    float* s_red = sm + RED_OFF;
    int*   s_idx = (int*)(sm + IDX_OFF);

    int tid = threadIdx.x;
    int bx = blockIdx.x;
    int b = bx >> 1, half = bx & 1;
    int c0 = half * 16;               // this block's output-channel base
    int pnpn = pn * pn;

    // combine code-split argmax partials (+ histogram from half-0 only)
    for (int p = tid; p < pnpn; p += 256) {
        size_t tb = (size_t)(b * pnpn + p) * CS;
        float bvv = g_pv[tb]; int bii = g_pi[tb];
        for (int cs = 1; cs < CS; cs++) {
            float v = g_pv[tb + cs]; int i2 = g_pi[tb + cs];
            if (v > bvv || (v == bvv && i2 < bii)) { bvv = v; bii = i2; }
        }
        s_idx[p] = bii;
        if (last && half == 0) atomicAdd(&g_hist[bii], 1);
    }

    // load this block's 16 co of Phi weights (+ all 32 biases)
    {
        const float4* wsrc = (const float4*)(phiw + (size_t)k * 9216 + c0 * 288);
        float4* wdst = (float4*)s_w;
        for (int i = tid; i < 1152; i += 256) wdst[i] = wsrc[i];
        if (tid < 32) s_b[tid] = phib[k * 32 + tid];
    }
    for (int i = tid; i < 10400; i += 256) s_hup[i] = 0.f;

    if (!last && tid < 64) {
        int i = tid >> 2, off = (tid & 3) - 1;
        double src = (i + 0.5) * (double)pn / 16.0 - 0.5;
        double i0 = floor(src);
        double f = src - i0;
        double t = fabs(f - (double)off);
        double w;
        if (t <= 1.0)      w = (1.25 * t - 2.25) * t * t + 1.0;
        else if (t < 2.0)  w = (((t - 5.0) * t + 8.0) * t - 4.0) * (-0.75);
        else               w = 0.0;
        int j = (int)i0 + off;
        j = min(max(j, 0), pn - 1);
        s_wt[tid] = (float)w;
        s_jt[tid] = j;
    }
    __syncthreads();

    if (!last) {
        for (int t = tid; t < pnpn * 32; t += 256) {
            int p = t >> 5, c = t & 31;
            s_hs[t] = cb[(size_t)s_idx[p] * NC + c];
        }
        __syncthreads();
    }

    // build h_up (interior of halo'd image), all 32 channels
    if (last) {
        for (int o = tid; o < 8192; o += 256) {
            int c = o & 31, pix = o >> 5;
            int y = pix >> 4, x = pix & 15;
            s_hup[c * 325 + (y + 1) * 18 + (x + 1)] =
                cb[(size_t)s_idx[pix] * NC + c];
        }
    } else {
        for (int o = tid; o < 8192; o += 256) {
            int c = o & 31, pix = o >> 5;
            int y = pix >> 4, x = pix & 15;
            float acc = 0.f;
#pragma unroll
            for (int ty = 0; ty < 4; ty++) {
                float wy = s_wt[y * 4 + ty];
                int jy = s_jt[y * 4 + ty];
                const float* row = s_hs + (jy * pn) * 32 + c;
                float rs = 0.f;
#pragma unroll
                for (int tx = 0; tx < 4; tx++)
                    rs = fmaf(s_wt[x * 4 + tx], row[s_jt[x * 4 + tx] * 32], rs);
                acc = fmaf(wy, rs, acc);
            }
            s_hup[c * 325 + (y + 1) * 18 + (x + 1)] = acc;
        }
    }
    __syncthreads();

    // 3x3 conv: warp wi (0..7) owns co = c0 + 2wi + co2;
    // lane -> (y = lane>>1, xs = (lane&1)*8)
    int wi = tid >> 5, lane = tid & 31;
    int y = lane >> 1, xs = (lane & 1) * 8;
    float acc[2][8];
#pragma unroll
    for (int a = 0; a < 2; a++)
#pragma unroll
        for (int o = 0; o < 8; o++) acc[a][o] = 0.f;

    for (int ci = 0; ci < 32; ci++) {
        float tp[3][10];
        const float* hp = s_hup + ci * 325 + y * 18 + xs;
#pragma unroll
        for (int r = 0; r < 3; r++)
#pragma unroll
            for (int cc = 0; cc < 10; cc++) tp[r][cc] = hp[r * 18 + cc];
#pragma unroll
        for (int co2 = 0; co2 < 2; co2++) {
            const float* wp = s_w + ((size_t)(wi * 2 + co2) * 32 + ci) * 9;
            float w0 = wp[0], w1 = wp[1], w2 = wp[2];
            float w3 = wp[3], w4 = wp[4], w5 = wp[5];
            float w6 = wp[6], w7 = wp[7], w8 = wp[8];
#pragma unroll
            for (int xo = 0; xo < 8; xo++) {
                float s = acc[co2][xo];
                s = fmaf(w0, tp[0][xo],     s);
                s = fmaf(w1, tp[0][xo + 1], s);
                s = fmaf(w2, tp[0][xo + 2], s);
                s = fmaf(w3, tp[1][xo],     s);
                s = fmaf(w4, tp[1][xo + 1], s);
                s = fmaf(w5, tp[1][xo + 2], s);
                s = fmaf(w6, tp[2][xo],     s);
                s = fmaf(w7, tp[2][xo + 1], s);
                s = fmaf(w8, tp[2][xo + 2], s);
                acc[co2][xo] = s;
            }
        }
    }

    // h = 0.5*h_up + 0.5*(conv + bias); update f_hat, f_rest; accumulate MSE
    float sq = 0.f;
    const float* finb = fin + (size_t)b * 8192;
    float* fhb = fhat + (size_t)b * 8192;
    float* frb = g_frest + (size_t)b * 8192;
#pragma unroll
    for (int co2 = 0; co2 < 2; co2++) {
        int co = c0 + wi * 2 + co2;
        float bias = s_b[co];
#pragma unroll
        for (int xo = 0; xo < 8; xo++) {
            int x = xs + xo;
            float conv = acc[co2][xo] + bias;
            float hu = s_hup[co * 325 + (y + 1) * 18 + (x + 1)];
            float h = 0.5f * hu + 0.5f * conv;
            int g = co * 256 + y * 16 + x;
            float fh = fhb[g] + h;
            fhb[g] = fh;
            frb[g] = frb[g] - h;
            float d = fh - finb[g];
            sq = fmaf(d, d, sq);
        }
    }
#pragma unroll
    for (int o = 16; o; o >>= 1) sq += __shfl_down_sync(0xffffffffu, sq, o);
    if (lane == 0) s_red[wi] = sq;
    __syncthreads();
    if (tid == 0) {
        float s = 0.f;
        for (int i = 0; i < 8; i++) s += s_red[i];
        g_part[si * 2 * NB + bx] = s;
    }

    // tail: next-scale tokens for this block's 16 channels (f_rest just updated)
    if (next_pn) {
        int npp = next_pn * next_pn;
        for (int t = tid; t < npp * 16; t += 256) {
            int cl = t & 15, p = t >> 4;
            int c = c0 + cl;
            int py = p / next_pn, px = p - py * next_pn;
            int ys = (py * HW) / next_pn, ye = ((py + 1) * HW + next_pn - 1) / next_pn;
            int xs2 = (px * HW) / next_pn, xe = ((px + 1) * HW + next_pn - 1) / next_pn;
            const float* bc = frb + c * 256;
            float s = 0.f;
            for (int yy = ys; yy < ye; yy++)
                for (int xx = xs2; xx < xe; xx++) s += bc[yy * 16 + xx];
            g_x[(size_t)(b * npp + p) * NC + c] =
                s / (float)((ye - ys) * (xe - xs2));
        }
    }
}

// ---------------- finalize: loss + perplexity ----------------
__global__ void k_final(float* __restrict__ out, int out_size) {
    __shared__ float sr[256];
    int tid = threadIdx.x;
    float s = 0.f;
    for (int i = tid; i < 10 * 2 * NB; i += 256) s += g_part[i];
    sr[tid] = s;
    __syncthreads();
    for (int o = 128; o; o >>= 1) {
        if (tid < o) sr[tid] += sr[tid + o];
        __syncthreads();
    }
    float lossv = 0.f;
    if (tid == 0) lossv = sr[0] * (1.25f / (10.0f * (float)FSZ));
    __syncthreads();

    float e = 0.f;
    for (int i = tid; i < NE; i += 256) {
        float p = (float)g_hist[i] * (1.0f / 32768.0f);
        e += p * logf(p + 1e-10f);
    }
    sr[tid] = e;
    __syncthreads();
    for (int o = 128; o; o >>= 1) {
        if (tid < o) sr[tid] += sr[tid + o];
        __syncthreads();
    }
    if (tid == 0) {
        out[out_size - 2] = lossv;
        out[out_size - 1] = expf(-sr[0]);
    }
}

// ---------------- launcher ----------------
extern "C" void kernel_launch(void* const* d_in, const int* in_sizes, int n_in,
                              void* d_out, int out_size) {
    // Identify inputs BY SIZE (robust to metadata ordering).
    const float* fin  = nullptr;
    const float* cb   = nullptr;
    const float* phiw = nullptr;
    const float* phib = nullptr;
    for (int i = 0; i < n_in; i++) {
        int sz = in_sizes[i];
        if      (sz == FSZ)        fin  = (const float*)d_in[i];
        else if (sz == NE * NC)    cb   = (const float*)d_in[i];
        else if (sz == 4*NC*NC*9)  phiw = (const float*)d_in[i];
        else if (sz == 4*NC)       phib = (const float*)d_in[i];
    }
    float* out = (float*)d_out;

    // PhiPartiallyShared tick schedule, replicating numpy float64 exactly.
    int phik[10];
    {
        double start = 1.0 / 12.0;
        double stop  = 1.0 - 1.0 / 12.0;
        double step  = (stop - start) / 3.0;
        double ticks[4];
        ticks[0] = start;
        ticks[1] = 1.0 * step + start;
        ticks[2] = 2.0 * step + start;
        ticks[3] = stop;
        for (int si = 0; si < 10; si++) {
            double v = (double)si / 9.0;
            int best = 0;
            double bd = fabs(ticks[0] - v);
            for (int kk = 1; kk < 4; kk++) {
                double d = fabs(ticks[kk] - v);
                if (d < bd) { bd = d; best = kk; }
            }
            phik[si] = best;
        }
    }

    cudaFuncSetAttribute(k_fused, cudaFuncAttributeMaxDynamicSharedMemorySize,
                         SMEM_FLOATS * 4);

    int initN = (FSZ > out_size ? FSZ : out_size);
    k_init<<<(initN + 255) / 256, 256>>>(fin, cb, out, out_size);

    for (int si = 0; si < 10; si++) {
        int pn = h_PNS[si];
        int ntok = NB * pn * pn;
        int last = (si == 9);
        int next_pn = (si < 8) ? h_PNS[si + 1] : 0;   // pn16 reads g_frest directly

        int CS;
        if (ntok >= 4608) {
            int tb = (ntok + 511) / 512;
            CS = 1;
            while (tb * CS < 296 && CS < 32) CS <<= 1;
            dim3 g(tb, CS);
            k_argmax_t<4><<<g, 128>>>(ntok, NE / CS, last ? 1 : 0);
        } else {
            int tb = ntok / 128;
            CS = 1;
            while (tb * CS < 296 && CS < 32) CS <<= 1;
            dim3 g(tb, CS);
            k_argmax_t<1><<<g, 128>>>(ntok, NE / CS, 0);
        }

        k_fused<<<2 * NB, 256, SMEM_FLOATS * 4>>>(fin, out, cb, phiw, phib,
                                                  si, pn, phik[si], last, CS,
                                                  next_pn);
    }
    k_final<<<1, 256>>>(out, out_size);
}